// round 1
// baseline (speedup 1.0000x reference)
#include <cuda_runtime.h>
#include <cstdint>
#include <cstddef>

// Problem constants (fixed by the dataset).
#define NEXP 16
#define NTOK 2048
#define DIM  1024
#define HID  4096

// Scratch for the hidden activations (E,N,H) fp32 = 512 MB.
// __device__ global: allowed (no runtime allocation).
__device__ float g_hidden[(size_t)NEXP * NTOK * HID];

// ---------------------------------------------------------------------------
// helpers
// ---------------------------------------------------------------------------
__device__ __forceinline__ uint32_t f2tf32(float f) {
    uint32_t u;
    asm("cvt.rna.tf32.f32 %0, %1;" : "=r"(u) : "f"(f));
    return u;
}

__device__ __forceinline__ void cp_async16(uint32_t smem, const void* gmem) {
    asm volatile("cp.async.cg.shared.global [%0], [%1], 16;\n"
                 :: "r"(smem), "l"(gmem));
}
__device__ __forceinline__ void cp_commit() {
    asm volatile("cp.async.commit_group;\n");
}
template <int N>
__device__ __forceinline__ void cp_wait() {
    asm volatile("cp.async.wait_group %0;\n" :: "n"(N));
}

__device__ __forceinline__ void mma_tf32(float& c0, float& c1, float& c2, float& c3,
                                         uint32_t a0, uint32_t a1, uint32_t a2, uint32_t a3,
                                         uint32_t b0, uint32_t b1) {
    asm volatile(
        "mma.sync.aligned.m16n8k8.row.col.f32.tf32.tf32.f32 "
        "{%0,%1,%2,%3}, {%4,%5,%6,%7}, {%8,%9}, {%0,%1,%2,%3};"
        : "+f"(c0), "+f"(c1), "+f"(c2), "+f"(c3)
        : "r"(a0), "r"(a1), "r"(a2), "r"(a3), "r"(b0), "r"(b1));
}

__device__ __forceinline__ float gelu_exact(float v) {
    return 0.5f * v * (1.0f + erff(v * 0.7071067811865476f));
}

// ---------------------------------------------------------------------------
// Grouped GEMM: C[e] = op(A[e] @ B[e] + bias)
//   A: [E][M][K] row-major, B: [E][K][N] row-major, C: [E][M][N] row-major
//   FIRST=true : A = x param,   C = g_hidden, op = exact GELU   (M=2048,N=4096,K=1024)
//   FIRST=false: A = g_hidden,  C = out param, op = identity    (M=2048,N=1024,K=4096)
// CTA tile 128x128x16, 256 threads, 8 warps as 4(row)x2(col), warp tile 32x64.
// ---------------------------------------------------------------------------
template <bool FIRST>
__global__ void __launch_bounds__(256)
moe_gemm_tf32(const float* __restrict__ Ap,
              const float* __restrict__ Bp,
              const float* __restrict__ bias,
              float* __restrict__ Cp,
              int M, int N, int K)
{
    constexpr int BM = 128, BN = 128, BK = 16;
    constexpr int ASTR = BK + 4;   // 20 floats / row  -> conflict-free A frags
    constexpr int BSTR = BN + 8;   // 136 floats / row -> conflict-free B frags
    constexpr int ABUF = BM * ASTR;       // floats per A buffer
    constexpr int BBUF = BK * BSTR;       // floats per B buffer

    __shared__ float As[2][ABUF];
    __shared__ float Bs[2][BBUF];

    const int e  = blockIdx.z;
    const int bm = blockIdx.y * BM;
    const int bn = blockIdx.x * BN;

    const float* Abase = FIRST ? Ap : g_hidden;
    float*       Cbase = FIRST ? g_hidden : Cp;

    const float* Ae = Abase + (size_t)e * M * K + (size_t)bm * K;
    const float* Be = Bp    + (size_t)e * K * N + bn;
    float*       Ce = Cbase + (size_t)e * M * N + (size_t)bm * N + bn;

    const int tid  = threadIdx.x;
    const int lane = tid & 31;
    const int warp = tid >> 5;
    const int wr   = warp & 3;   // warp row (4 x 32 rows)
    const int wc   = warp >> 2;  // warp col (2 x 64 cols)

    // ---- global->shared load mapping (float4 granularity) ----
    // A tile: 128 rows x 16 cols = 512 float4; thread handles rows tid>>2 and +64.
    const float* agp = Ae + (size_t)(tid >> 2) * K + (tid & 3) * 4;
    // B tile: 16 rows x 128 cols = 512 float4; thread handles rows tid>>5 and +8.
    const float* bgp = Be + (size_t)(tid >> 5) * N + (tid & 31) * 4;

    const uint32_t as_w = (uint32_t)__cvta_generic_to_shared(&As[0][0]) +
                          (((tid >> 2) * ASTR + (tid & 3) * 4) << 2);
    const uint32_t bs_w = (uint32_t)__cvta_generic_to_shared(&Bs[0][0]) +
                          (((tid >> 5) * BSTR + (tid & 31) * 4) << 2);
    constexpr uint32_t ABUF_B = ABUF * 4;
    constexpr uint32_t BBUF_B = BBUF * 4;

    float acc[2][8][4];
    #pragma unroll
    for (int mt = 0; mt < 2; mt++)
        #pragma unroll
        for (int nt = 0; nt < 8; nt++)
            #pragma unroll
            for (int i = 0; i < 4; i++)
                acc[mt][nt][i] = 0.0f;

    const int KT = K / BK;

    // prologue: stage tile 0 into buffer 0
    {
        cp_async16(as_w,                       agp);
        cp_async16(as_w + 64u * ASTR * 4u,     agp + (size_t)64 * K);
        cp_async16(bs_w,                       bgp);
        cp_async16(bs_w + 8u * BSTR * 4u,      bgp + (size_t)8 * N);
        cp_commit();
    }

    int buf = 0;
    const int arow = wr * 32 + (lane >> 2);
    const int acol = lane & 3;
    const int bnn  = wc * 64 + (lane >> 2);
    const int bkk  = lane & 3;

    for (int kt = 0; kt < KT; kt++) {
        if (kt + 1 < KT) {
            const int nb = buf ^ 1;
            const float* ag = agp + (size_t)(kt + 1) * BK;
            const float* bg = bgp + (size_t)(kt + 1) * BK * N;
            cp_async16(as_w + nb * ABUF_B,                    ag);
            cp_async16(as_w + nb * ABUF_B + 64u * ASTR * 4u,  ag + (size_t)64 * K);
            cp_async16(bs_w + nb * BBUF_B,                    bg);
            cp_async16(bs_w + nb * BBUF_B + 8u * BSTR * 4u,   bg + (size_t)8 * N);
        }
        cp_commit();
        cp_wait<1>();
        __syncthreads();

        const float* ab = &As[buf][0];
        const float* bb = &Bs[buf][0];

        #pragma unroll
        for (int kk = 0; kk < 2; kk++) {
            uint32_t af[2][4];
            #pragma unroll
            for (int mt = 0; mt < 2; mt++) {
                const float* p = ab + (arow + mt * 16) * ASTR + kk * 8 + acol;
                af[mt][0] = f2tf32(p[0]);
                af[mt][1] = f2tf32(p[8 * ASTR]);
                af[mt][2] = f2tf32(p[4]);
                af[mt][3] = f2tf32(p[8 * ASTR + 4]);
            }
            #pragma unroll
            for (int nt = 0; nt < 8; nt++) {
                const float* q = bb + (kk * 8 + bkk) * BSTR + bnn + nt * 8;
                uint32_t b0 = f2tf32(q[0]);
                uint32_t b1 = f2tf32(q[4 * BSTR]);
                #pragma unroll
                for (int mt = 0; mt < 2; mt++) {
                    mma_tf32(acc[mt][nt][0], acc[mt][nt][1],
                             acc[mt][nt][2], acc[mt][nt][3],
                             af[mt][0], af[mt][1], af[mt][2], af[mt][3],
                             b0, b1);
                }
            }
        }
        __syncthreads();
        buf ^= 1;
    }

    // ---- epilogue: bias (+ GELU for layer 1), write fp32 ----
    #pragma unroll
    for (int mt = 0; mt < 2; mt++) {
        const int r0 = wr * 32 + mt * 16 + (lane >> 2);
        #pragma unroll
        for (int nt = 0; nt < 8; nt++) {
            const int c0 = wc * 64 + nt * 8 + (lane & 3) * 2;
            const float bv0 = bias[bn + c0];
            const float bv1 = bias[bn + c0 + 1];

            float v0 = acc[mt][nt][0] + bv0;
            float v1 = acc[mt][nt][1] + bv1;
            float v2 = acc[mt][nt][2] + bv0;
            float v3 = acc[mt][nt][3] + bv1;
            if (FIRST) {
                v0 = gelu_exact(v0); v1 = gelu_exact(v1);
                v2 = gelu_exact(v2); v3 = gelu_exact(v3);
            }
            *reinterpret_cast<float2*>(Ce + (size_t)r0 * N + c0) =
                make_float2(v0, v1);
            *reinterpret_cast<float2*>(Ce + (size_t)(r0 + 8) * N + c0) =
                make_float2(v2, v3);
        }
    }
}

// ---------------------------------------------------------------------------
// launch
// ---------------------------------------------------------------------------
extern "C" void kernel_launch(void* const* d_in, const int* in_sizes, int n_in,
                              void* d_out, int out_size)
{
    const float* x  = (const float*)d_in[0];   // (E, N, D)
    const float* w1 = (const float*)d_in[1];   // (E, D, H)
    const float* w2 = (const float*)d_in[2];   // (E, H, D)
    const float* b1 = (const float*)d_in[3];   // (H)
    const float* b2 = (const float*)d_in[4];   // (D)
    float* out = (float*)d_out;                // (E, N, D)

    dim3 block(256);

    // Layer 1: hidden = gelu(x @ w1 + b1)   M=2048, N=H=4096, K=D=1024
    dim3 g1(HID / 128, NTOK / 128, NEXP);
    moe_gemm_tf32<true><<<g1, block>>>(x, w1, b1, nullptr, NTOK, HID, DIM);

    // Layer 2: out = hidden @ w2 + b2       M=2048, N=D=1024, K=H=4096
    dim3 g2(DIM / 128, NTOK / 128, NEXP);
    moe_gemm_tf32<false><<<g2, block>>>(nullptr, w2, b2, out, NTOK, DIM, HID);
}

// round 4
// speedup vs baseline: 2.3728x; 2.3728x over previous
#include <cuda_runtime.h>
#include <cuda_fp16.h>
#include <cstdint>
#include <cstddef>

// Problem constants.
#define NEXP 16
#define NTOK 2048
#define DIM  1024
#define HID  4096

// Static device scratch (no runtime allocation).
__device__ __half g_xh [(size_t)NEXP * NTOK * DIM];   //  64 MB  x    fp16 [E][N][D]
__device__ __half g_w1t[(size_t)NEXP * HID * DIM];    // 128 MB  w1^T fp16 [E][H][D]
__device__ __half g_w2t[(size_t)NEXP * DIM * HID];    // 128 MB  w2^T fp16 [E][D][H]
__device__ __half g_hid[(size_t)NEXP * NTOK * HID];   // 256 MB  hidden fp16 [E][N][H]

// ---------------------------------------------------------------------------
// helpers
// ---------------------------------------------------------------------------
__device__ __forceinline__ uint32_t smem_u32(const void* p) {
    uint32_t a;
    asm("{ .reg .u64 t; cvta.to.shared.u64 t, %1; cvt.u32.u64 %0, t; }"
        : "=r"(a) : "l"(p));
    return a;
}

__device__ __forceinline__ void cp_async16(uint32_t smem, const void* gmem) {
    asm volatile("cp.async.cg.shared.global [%0], [%1], 16;\n"
                 :: "r"(smem), "l"(gmem));
}
__device__ __forceinline__ void cp_commit() {
    asm volatile("cp.async.commit_group;\n");
}
template <int N>
__device__ __forceinline__ void cp_wait() {
    asm volatile("cp.async.wait_group %0;\n" :: "n"(N));
}

__device__ __forceinline__ void ldsm_x4(uint32_t* r, uint32_t addr) {
    asm volatile("ldmatrix.sync.aligned.m8n8.x4.shared.b16 {%0,%1,%2,%3}, [%4];"
                 : "=r"(r[0]), "=r"(r[1]), "=r"(r[2]), "=r"(r[3]) : "r"(addr));
}

__device__ __forceinline__ void mma_f16(float* c, const uint32_t* a,
                                        uint32_t b0, uint32_t b1) {
    asm volatile(
        "mma.sync.aligned.m16n8k16.row.col.f32.f16.f16.f32 "
        "{%0,%1,%2,%3}, {%4,%5,%6,%7}, {%8,%9}, {%0,%1,%2,%3};"
        : "+f"(c[0]), "+f"(c[1]), "+f"(c[2]), "+f"(c[3])
        : "r"(a[0]), "r"(a[1]), "r"(a[2]), "r"(a[3]), "r"(b0), "r"(b1));
}

__device__ __forceinline__ float gelu_exact(float v) {
    return 0.5f * v * (1.0f + erff(v * 0.7071067811865476f));
}

// ---------------------------------------------------------------------------
// pre-pass kernels
// ---------------------------------------------------------------------------
__global__ void cvt_x_kernel(const float4* __restrict__ in, int n4) {
    int i = blockIdx.x * blockDim.x + threadIdx.x;
    if (i < n4) {
        float4 v = in[i];
        __half2 a = __floats2half2_rn(v.x, v.y);
        __half2 b = __floats2half2_rn(v.z, v.w);
        uint2 o;
        o.x = *reinterpret_cast<uint32_t*>(&a);
        o.y = *reinterpret_cast<uint32_t*>(&b);
        reinterpret_cast<uint2*>(g_xh)[i] = o;
    }
}

// in: [E][R][C] f32  ->  out: [E][C][R] f16
template <bool W1>
__global__ void transpose_cvt(const float* __restrict__ in, int R, int C) {
    __shared__ float tile[32][33];
    const int e = blockIdx.z;
    const int c0 = blockIdx.x * 32, r0 = blockIdx.y * 32;
    const float* src = in + (size_t)e * R * C;
    __half* dst = (W1 ? g_w1t : g_w2t) + (size_t)e * C * R;
    const int tx = threadIdx.x, ty = threadIdx.y;   // (32, 8)
    #pragma unroll
    for (int i = 0; i < 32; i += 8)
        tile[ty + i][tx] = src[(size_t)(r0 + ty + i) * C + c0 + tx];
    __syncthreads();
    #pragma unroll
    for (int i = 0; i < 32; i += 8)
        dst[(size_t)(c0 + ty + i) * R + r0 + tx] = __float2half_rn(tile[tx][ty + i]);
}

// ---------------------------------------------------------------------------
// fp16 HMMA grouped GEMM:  C[e] = op(A[e] @ B[e]^T + bias)
//   A: [E][M][K] fp16 K-major, B: [E][N][K] fp16 K-major
//   FIRST : A=g_xh,  B=g_w1t, C=g_hid (fp16, GELU)   M=2048 N=4096 K=1024
//   !FIRST: A=g_hid, B=g_w2t, C=out   (fp32, bias)   M=2048 N=1024 K=4096
// CTA 128x128, BK=64 (128B rows). 8 warps (2 mrow x 4 ncol), warp tile 64x32.
// Swizzle: byte offset row*128 + (kbyte ^ ((row&7)*16)).
// ---------------------------------------------------------------------------
#define BM 128
#define BN 128
#define BK 64
#define ASTAGE (BM * BK * 2)           // 16 KB
#define BSTAGE (BN * BK * 2)           // 16 KB
#define STAGEB (ASTAGE + BSTAGE)       // 32 KB
#define SMEM_BYTES (2 * STAGEB + 1024) // 64 KB + align slack

template <bool FIRST>
__global__ void __launch_bounds__(256, 2)
moe_hmma(const float* __restrict__ bias, float* __restrict__ Cf)
{
    constexpr int N = FIRST ? HID : DIM;
    constexpr int K = FIRST ? DIM : HID;
    constexpr int KT = K / BK;

    extern __shared__ char smem_raw[];
    uint32_t sb = smem_u32(smem_raw);
    sb = (sb + 1023u) & ~1023u;

    const int tid  = threadIdx.x;
    const int lane = tid & 31;
    const int warp = tid >> 5;
    const int wr   = warp >> 2;          // 0..1 : 64-row band
    const int wc   = warp & 3;           // 0..3 : 32-col band

    const int e  = blockIdx.z;
    const int bm = blockIdx.y * BM;
    const int bn = blockIdx.x * BN;

    const __half* Abase = FIRST ? g_xh  : g_hid;
    const __half* Bbase = FIRST ? g_w1t : g_w2t;
    const char* Ag = reinterpret_cast<const char*>(Abase + ((size_t)e * NTOK + bm) * K);
    const char* Bg = reinterpret_cast<const char*>(Bbase + ((size_t)e * N    + bn) * K);

    // ---- loader constants: unit u = tid + 256*i, row=u>>3, cb=(u&7)*16 ----
    // swizzled smem offset = row*128 + (cb ^ ((row&7)*16))
    uint32_t ld_s[4];
    uint32_t ld_g[4];
    #pragma unroll
    for (int i = 0; i < 4; i++) {
        const int u   = tid + 256 * i;
        const int row = u >> 3;
        const int cb  = (u & 7) * 16;
        ld_s[i] = row * 128 + (cb ^ ((row & 7) * 16));
        ld_g[i] = row * (K * 2) + cb;          // gmem byte offset at kt=0
    }

    auto load_tile = [&](int s, int kt) {
        const uint32_t ab = sb + s * STAGEB;
        const uint32_t bb = ab + ASTAGE;
        const uint32_t kb = (uint32_t)kt * (BK * 2);
        #pragma unroll
        for (int i = 0; i < 4; i++)
            cp_async16(ab + ld_s[i], Ag + ld_g[i] + kb);
        #pragma unroll
        for (int i = 0; i < 4; i++)
            cp_async16(bb + ld_s[i], Bg + ld_g[i] + kb);
    };

    // ---- ldmatrix per-lane constants ----
    const int grp  = lane >> 3;          // matrix index group
    const int lrow = lane & 7;
    const int xm   = lrow * 16;          // swizzle XOR for this lane's rows
    // A: matrices (rows0-7,klo)(rows8-15,klo)(rows0-7,khi)(rows8-15,khi)
    const int a_row0 = wr * 64 + (grp & 1) * 8 + lrow;
    const int a_kh   = (grp >> 1) * 16;
    // B: matrices (n0-7,klo)(n0-7,khi)(n8-15,klo)(n8-15,khi)
    const int b_row0 = wc * 32 + (grp >> 1) * 8 + lrow;
    const int b_kh   = (grp & 1) * 16;

    float acc[4][4][4];
    #pragma unroll
    for (int mt = 0; mt < 4; mt++)
        #pragma unroll
        for (int nt = 0; nt < 4; nt++)
            #pragma unroll
            for (int i = 0; i < 4; i++)
                acc[mt][nt][i] = 0.0f;

    load_tile(0, 0); cp_commit();
    load_tile(1, 1); cp_commit();

    for (int kt = 0; kt < KT; kt++) {
        const int s = kt & 1;
        cp_wait<1>();
        __syncthreads();

        const uint32_t aS = sb + s * STAGEB;
        const uint32_t bS = aS + ASTAGE;

        #pragma unroll
        for (int kk = 0; kk < 4; kk++) {
            uint32_t af[4][4];
            #pragma unroll
            for (int mt = 0; mt < 4; mt++)
                ldsm_x4(af[mt], aS + (a_row0 + mt * 16) * 128 +
                                   ((kk * 32 + a_kh) ^ xm));
            uint32_t bf[2][4];
            #pragma unroll
            for (int p = 0; p < 2; p++)
                ldsm_x4(bf[p], bS + (b_row0 + p * 16) * 128 +
                                  ((kk * 32 + b_kh) ^ xm));
            #pragma unroll
            for (int mt = 0; mt < 4; mt++) {
                mma_f16(acc[mt][0], af[mt], bf[0][0], bf[0][1]);
                mma_f16(acc[mt][1], af[mt], bf[0][2], bf[0][3]);
                mma_f16(acc[mt][2], af[mt], bf[1][0], bf[1][1]);
                mma_f16(acc[mt][3], af[mt], bf[1][2], bf[1][3]);
            }
        }

        __syncthreads();
        if (kt + 2 < KT) load_tile(s, kt + 2);
        cp_commit();                       // keep group accounting uniform
    }

    // ---- epilogue ----
    const int erow = bm + wr * 64 + (lane >> 2);
    const int ecol = bn + wc * 32 + (lane & 3) * 2;
    #pragma unroll
    for (int mt = 0; mt < 4; mt++) {
        #pragma unroll
        for (int nt = 0; nt < 4; nt++) {
            const int col = ecol + nt * 8;
            const float bv0 = bias[col];
            const float bv1 = bias[col + 1];
            float v0 = acc[mt][nt][0] + bv0;
            float v1 = acc[mt][nt][1] + bv1;
            float v2 = acc[mt][nt][2] + bv0;
            float v3 = acc[mt][nt][3] + bv1;
            const int r0 = erow + mt * 16;
            if (FIRST) {
                v0 = gelu_exact(v0); v1 = gelu_exact(v1);
                v2 = gelu_exact(v2); v3 = gelu_exact(v3);
                __half2 h0 = __floats2half2_rn(v0, v1);
                __half2 h1 = __floats2half2_rn(v2, v3);
                __half* base = g_hid + (size_t)e * NTOK * N;
                *reinterpret_cast<__half2*>(base + (size_t)r0 * N + col) = h0;
                *reinterpret_cast<__half2*>(base + (size_t)(r0 + 8) * N + col) = h1;
            } else {
                float* base = Cf + (size_t)e * NTOK * N;
                *reinterpret_cast<float2*>(base + (size_t)r0 * N + col) =
                    make_float2(v0, v1);
                *reinterpret_cast<float2*>(base + (size_t)(r0 + 8) * N + col) =
                    make_float2(v2, v3);
            }
        }
    }
}

// ---------------------------------------------------------------------------
// launch
// ---------------------------------------------------------------------------
extern "C" void kernel_launch(void* const* d_in, const int* in_sizes, int n_in,
                              void* d_out, int out_size)
{
    const float* x  = (const float*)d_in[0];   // (E, N, D)
    const float* w1 = (const float*)d_in[1];   // (E, D, H)
    const float* w2 = (const float*)d_in[2];   // (E, H, D)
    const float* b1 = (const float*)d_in[3];   // (H)
    const float* b2 = (const float*)d_in[4];   // (D)
    float* out = (float*)d_out;                // (E, N, D)

    cudaFuncSetAttribute(moe_hmma<true>,
        cudaFuncAttributeMaxDynamicSharedMemorySize, SMEM_BYTES);
    cudaFuncSetAttribute(moe_hmma<false>,
        cudaFuncAttributeMaxDynamicSharedMemorySize, SMEM_BYTES);

    // pre-pass: fp16 conversions (+ weight transposes to K-major)
    const int n4 = (NEXP * NTOK * DIM) / 4;
    cvt_x_kernel<<<n4 / 256, 256>>>((const float4*)x, n4);
    transpose_cvt<true ><<<dim3(HID / 32, DIM / 32, NEXP), dim3(32, 8)>>>(w1, DIM, HID);
    transpose_cvt<false><<<dim3(DIM / 32, HID / 32, NEXP), dim3(32, 8)>>>(w2, HID, DIM);

    // layer 1: hidden = gelu(x @ w1 + b1)
    moe_hmma<true ><<<dim3(HID / BN, NTOK / BM, NEXP), 256, SMEM_BYTES>>>(b1, nullptr);
    // layer 2: out = hidden @ w2 + b2
    moe_hmma<false><<<dim3(DIM / BN, NTOK / BM, NEXP), 256, SMEM_BYTES>>>(b2, out);
}